// round 1
// baseline (speedup 1.0000x reference)
#include <cuda_runtime.h>
#include <math.h>
#include <stdint.h>

#define DD 128
#define MAXN 100000

// Scratch: transformed features T[4][N][128] and gate pre-activations G[4][N]
__device__ float g_T[(size_t)4 * MAXN * DD];
__device__ float g_G[(size_t)4 * MAXN];

// ---------- packed fp32x2 helpers (sm_100+) ----------
__device__ __forceinline__ unsigned long long pack2(float a, float b) {
    unsigned long long r;
    asm("mov.b64 %0, {%1, %2};" : "=l"(r) : "f"(a), "f"(b));
    return r;
}
__device__ __forceinline__ void unpack2(unsigned long long v, float& a, float& b) {
    asm("mov.b64 {%0, %1}, %2;" : "=f"(a), "=f"(b) : "l"(v));
}
__device__ __forceinline__ void fma2(unsigned long long& d, unsigned long long a,
                                     unsigned long long b) {
    asm("fma.rn.f32x2 %0, %1, %2, %0;" : "+l"(d) : "l"(a), "l"(b));
}

// ---------------------------------------------------------------------------
// Transform kernel: T[t] = inp @ W[t]^T   (W stored [out=128][in=128])
// Block computes a 128(node) x 128(col) tile for one type t = blockIdx.y.
// Full K=128 resident in smem; per-thread 8x8 micro-tile with f32x2 packing.
// smem: As[128][128] (row-major, natural), Bs[128][132] (k-major, W transposed)
// ---------------------------------------------------------------------------
#define BP 132
#define SMEM_BYTES ((128 * 128 + 128 * BP) * 4)

__global__ __launch_bounds__(256, 1)
void transform_kernel(const float* __restrict__ inp,
                      const float* __restrict__ W0, const float* __restrict__ W1,
                      const float* __restrict__ W2, const float* __restrict__ W3,
                      int N)
{
    extern __shared__ float smem[];
    float* As = smem;               // [128][128]  As[row][k]
    float* Bs = smem + 128 * 128;   // [128][BP]   Bs[k][j]

    const float* W = (blockIdx.y == 0) ? W0 : (blockIdx.y == 1) ? W1
                   : (blockIdx.y == 2) ? W2 : W3;
    float* Tout = g_T + (size_t)blockIdx.y * N * DD;

    const int tid = threadIdx.x;
    const int tx = tid & 15;        // col group 0..15
    const int ty = tid >> 4;        // row group 0..15
    const int rowBase = blockIdx.x * 128;

    // ---- load A tile (rows of inp), natural layout, float4 ----
    const float4 zero4 = make_float4(0.f, 0.f, 0.f, 0.f);
    #pragma unroll
    for (int i = tid; i < 128 * 32; i += 256) {   // 4096 float4
        int row = i >> 5, c4 = i & 31;
        float4 v = zero4;
        int gr = rowBase + row;
        if (gr < N) v = *(const float4*)(inp + (size_t)gr * DD + c4 * 4);
        *(float4*)&As[row * 128 + c4 * 4] = v;
    }
    // ---- load W transposed into Bs[k][j] ----
    #pragma unroll
    for (int i = tid; i < 128 * 32; i += 256) {
        int j = i >> 5, kb = i & 31;
        float4 v = *(const float4*)(W + j * 128 + kb * 4);
        Bs[(kb * 4 + 0) * BP + j] = v.x;
        Bs[(kb * 4 + 1) * BP + j] = v.y;
        Bs[(kb * 4 + 2) * BP + j] = v.z;
        Bs[(kb * 4 + 3) * BP + j] = v.w;
    }
    __syncthreads();

    // ---- compute: acc[i][p] over rows {ty*4..+3, 64+ty*4..+3},
    //      col-pairs within {tx*4..+3, 64+tx*4..+3} ----
    unsigned long long acc[8][4];
    #pragma unroll
    for (int i = 0; i < 8; i++)
        #pragma unroll
        for (int p = 0; p < 4; p++) acc[i][p] = 0ull;

    #pragma unroll 4
    for (int k = 0; k < 128; k++) {
        float4 b0 = *(const float4*)&Bs[k * BP + tx * 4];
        float4 b1 = *(const float4*)&Bs[k * BP + 64 + tx * 4];
        unsigned long long bp[4];
        bp[0] = pack2(b0.x, b0.y);
        bp[1] = pack2(b0.z, b0.w);
        bp[2] = pack2(b1.x, b1.y);
        bp[3] = pack2(b1.z, b1.w);
        #pragma unroll
        for (int i = 0; i < 8; i++) {
            int r = (i < 4) ? (ty * 4 + i) : (64 + ty * 4 + (i - 4));
            float a = As[r * 128 + k];
            unsigned long long ap = pack2(a, a);
            #pragma unroll
            for (int p = 0; p < 4; p++) fma2(acc[i][p], ap, bp[p]);
        }
    }

    // ---- epilogue ----
    #pragma unroll
    for (int i = 0; i < 8; i++) {
        int r = (i < 4) ? (ty * 4 + i) : (64 + ty * 4 + (i - 4));
        int gr = rowBase + r;
        if (gr >= N) continue;
        float4 o;
        unpack2(acc[i][0], o.x, o.y);
        unpack2(acc[i][1], o.z, o.w);
        *(float4*)(Tout + (size_t)gr * DD + tx * 4) = o;
        unpack2(acc[i][2], o.x, o.y);
        unpack2(acc[i][3], o.z, o.w);
        *(float4*)(Tout + (size_t)gr * DD + 64 + tx * 4) = o;
    }
}

// ---------------------------------------------------------------------------
// Gate kernel: G[t][n] = dot(inp[n], gate_w[t]).  One warp per node.
// ---------------------------------------------------------------------------
__global__ __launch_bounds__(256)
void gate_kernel(const float* __restrict__ inp,
                 const float* __restrict__ g0, const float* __restrict__ g1,
                 const float* __restrict__ g2, const float* __restrict__ g3,
                 int N)
{
    __shared__ float gw[4 * 128];
    int tid = threadIdx.x;
    for (int i = tid; i < 512; i += 256) {
        const float* gp = (i < 128) ? g0 : (i < 256) ? g1 : (i < 384) ? g2 : g3;
        gw[i] = gp[i & 127];
    }
    __syncthreads();

    int warp = tid >> 5, lane = tid & 31;
    int node = blockIdx.x * 8 + warp;
    if (node >= N) return;
    float4 x = *(const float4*)(inp + (size_t)node * DD + lane * 4);
    #pragma unroll
    for (int t = 0; t < 4; t++) {
        float4 w = *(const float4*)(gw + t * 128 + lane * 4);
        float d = x.x * w.x + x.y * w.y + x.z * w.z + x.w * w.w;
        #pragma unroll
        for (int o = 16; o; o >>= 1) d += __shfl_xor_sync(0xffffffffu, d, o);
        if (lane == 0) g_G[(size_t)t * N + node] = d;
    }
}

// ---------------------------------------------------------------------------
// Edge kernel: one warp per edge. Gather T row, add relation bias (types 0/1),
// sigmoid gate, vector-RED scatter-add into out[tgt].
// ---------------------------------------------------------------------------
__global__ __launch_bounds__(256)
void edge_kernel(const int* __restrict__ deprel, const int* __restrict__ deparc,
                 const int* __restrict__ eidx,
                 const float* __restrict__ b_in, const float* __restrict__ b_in_gate,
                 const float* __restrict__ b_out, const float* __restrict__ b_out_gate,
                 float* __restrict__ out, int N, int E)
{
    int e = (int)((blockIdx.x * 256u + threadIdx.x) >> 5);
    if (e >= E) return;
    int lane = threadIdx.x & 31;

    int t  = __ldg(deparc + e);
    int s  = __ldg(eidx + e);
    int tg = __ldg(eidx + E + e);

    float gpre = g_G[(size_t)t * N + s];
    float4 m = *(const float4*)(g_T + ((size_t)t * N + s) * DD + lane * 4);

    float bg = 0.f;
    if (t < 2) {
        int r = __ldg(deprel + e);
        const float* bb = (t == 0) ? b_in : b_out;
        float4 b4 = *(const float4*)(bb + (size_t)r * DD + lane * 4);
        m.x += b4.x; m.y += b4.y; m.z += b4.z; m.w += b4.w;
        bg = (t == 0) ? __ldg(b_in_gate + r) : __ldg(b_out_gate + r);
    }
    float gate = 1.f / (1.f + expf(-(gpre + bg)));
    m.x *= gate; m.y *= gate; m.z *= gate; m.w *= gate;

    float* op = out + (size_t)tg * DD + lane * 4;
    asm volatile("red.global.add.v4.f32 [%0], {%1, %2, %3, %4};"
                 :: "l"(op), "f"(m.x), "f"(m.y), "f"(m.z), "f"(m.w)
                 : "memory");
}

// ---------------------------------------------------------------------------
extern "C" void kernel_launch(void* const* d_in, const int* in_sizes, int n_in,
                              void* d_out, int out_size)
{
    const float* inp         = (const float*)d_in[0];
    const int*   deprel      = (const int*)  d_in[1];
    const int*   deparc      = (const int*)  d_in[2];
    const int*   eidx        = (const int*)  d_in[3];
    const float* V_in        = (const float*)d_in[4];
    const float* b_in        = (const float*)d_in[5];
    const float* V_in_gate   = (const float*)d_in[6];
    const float* b_in_gate   = (const float*)d_in[7];
    const float* V_out       = (const float*)d_in[8];
    const float* b_out       = (const float*)d_in[9];
    const float* V_out_gate  = (const float*)d_in[10];
    const float* b_out_gate  = (const float*)d_in[11];
    const float* W_self      = (const float*)d_in[12];
    const float* W_self_gate = (const float*)d_in[13];
    const float* W_norel     = (const float*)d_in[14];
    const float* W_norel_gate= (const float*)d_in[15];
    (void)W_norel_gate; (void)n_in;

    const int N = in_sizes[0] / DD;
    const int E = in_sizes[1];
    float* out = (float*)d_out;

    cudaFuncSetAttribute(transform_kernel,
                         cudaFuncAttributeMaxDynamicSharedMemorySize, SMEM_BYTES);

    cudaMemsetAsync(d_out, 0, (size_t)out_size * sizeof(float), 0);

    dim3 tgrid((N + 127) / 128, 4);
    transform_kernel<<<tgrid, 256, SMEM_BYTES>>>(inp, V_in, V_out, W_self, W_norel, N);

    gate_kernel<<<(N + 7) / 8, 256>>>(inp, V_in_gate, V_out_gate,
                                      W_self_gate, W_norel_gate, N);

    int eblocks = (E * 32 + 255) / 256;
    edge_kernel<<<eblocks, 256>>>(deprel, deparc, eidx,
                                  b_in, b_in_gate, b_out, b_out_gate,
                                  out, N, E);
}

// round 3
// speedup vs baseline: 1.5353x; 1.5353x over previous
#include <cuda_runtime.h>
#include <cuda_bf16.h>
#include <math.h>
#include <stdint.h>

#define DD 128
#define MAXN 100000
#define MAXT ((MAXN + 127) / 128)          // row tiles
#define TILE_BYTES 32768                    // 128-row tile: 2 ktiles x 16KB (bf16 SW128)

// Scratch
__device__ float g_T[(size_t)4 * MAXN * DD];
__device__ float g_G[(size_t)4 * MAXN];
__device__ __align__(16) unsigned char g_Ah[(size_t)MAXT * TILE_BYTES];
__device__ __align__(16) unsigned char g_Al[(size_t)MAXT * TILE_BYTES];
__device__ __align__(16) unsigned char g_Wh[(size_t)4 * TILE_BYTES];
__device__ __align__(16) unsigned char g_Wl[(size_t)4 * TILE_BYTES];

#define SWZ(x) ((x) ^ (((x) >> 3) & 0x70))

__device__ __forceinline__ uint32_t smem_u32(const void* p) {
    uint32_t a;
    asm("{ .reg .u64 t; cvta.to.shared.u64 t, %1; cvt.u32.u64 %0, t; }" : "=r"(a) : "l"(p));
    return a;
}
__device__ __forceinline__ void ldsm4(uint32_t* r, uint32_t addr) {
    asm volatile("ldmatrix.sync.aligned.m8n8.x4.shared.b16 {%0,%1,%2,%3}, [%4];"
                 : "=r"(r[0]), "=r"(r[1]), "=r"(r[2]), "=r"(r[3]) : "r"(addr));
}
__device__ __forceinline__ void mma_bf16(float* c, const uint32_t* a,
                                         uint32_t b0, uint32_t b1) {
    asm volatile("mma.sync.aligned.m16n8k16.row.col.f32.bf16.bf16.f32 "
                 "{%0,%1,%2,%3}, {%4,%5,%6,%7}, {%8,%9}, {%0,%1,%2,%3};"
                 : "+f"(c[0]), "+f"(c[1]), "+f"(c[2]), "+f"(c[3])
                 : "r"(a[0]), "r"(a[1]), "r"(a[2]), "r"(a[3]), "r"(b0), "r"(b1));
}

// ---------------------------------------------------------------------------
// prep_w: W[t] (f32 [128][128]) -> hi/lo bf16, swizzled tile layout
// ---------------------------------------------------------------------------
__global__ __launch_bounds__(256)
void prep_w(const float* __restrict__ W0, const float* __restrict__ W1,
            const float* __restrict__ W2, const float* __restrict__ W3)
{
    int g = blockIdx.x * 256 + threadIdx.x;
    int warp = g >> 5, lane = g & 31;
    if (warp >= 512) return;
    int t = warp >> 7, j = warp & 127;
    const float* W = (t == 0) ? W0 : (t == 1) ? W1 : (t == 2) ? W2 : W3;
    float4 x = *(const float4*)(W + (size_t)j * 128 + lane * 4);

    __nv_bfloat16 h[4], l[4];
    float xs[4] = {x.x, x.y, x.z, x.w};
    #pragma unroll
    for (int i = 0; i < 4; i++) {
        h[i] = __float2bfloat16(xs[i]);
        l[i] = __float2bfloat16(xs[i] - __bfloat162float(h[i]));
    }
    unsigned long long hp, lp;
    memcpy(&hp, h, 8); memcpy(&lp, l, 8);

    int ktile = lane >> 4;
    uint32_t sw = SWZ((uint32_t)(j * 128 + (lane & 15) * 8));
    size_t off = (size_t)(t * 2 + ktile) * 16384 + sw;
    *(unsigned long long*)(g_Wh + off) = hp;
    *(unsigned long long*)(g_Wl + off) = lp;
}

// ---------------------------------------------------------------------------
// prep_nodes: one warp per node; hi/lo bf16 split (swizzled) + 4 gate dots
// ---------------------------------------------------------------------------
__global__ __launch_bounds__(256)
void prep_nodes(const float* __restrict__ inp,
                const float* __restrict__ g0, const float* __restrict__ g1,
                const float* __restrict__ g2, const float* __restrict__ g3,
                int N)
{
    __shared__ float gw[4 * 128];
    int tid = threadIdx.x;
    for (int i = tid; i < 512; i += 256) {
        const float* gp = (i < 128) ? g0 : (i < 256) ? g1 : (i < 384) ? g2 : g3;
        gw[i] = gp[i & 127];
    }
    __syncthreads();

    int warp = tid >> 5, lane = tid & 31;
    int node = blockIdx.x * 8 + warp;
    if (node >= N) return;

    float4 x = *(const float4*)(inp + (size_t)node * DD + lane * 4);

    #pragma unroll
    for (int t = 0; t < 4; t++) {
        float4 w = *(const float4*)(gw + t * 128 + lane * 4);
        float d = x.x * w.x + x.y * w.y + x.z * w.z + x.w * w.w;
        #pragma unroll
        for (int o = 16; o; o >>= 1) d += __shfl_xor_sync(0xffffffffu, d, o);
        if (lane == 0) g_G[(size_t)t * N + node] = d;
    }

    __nv_bfloat16 h[4], l[4];
    float xs[4] = {x.x, x.y, x.z, x.w};
    #pragma unroll
    for (int i = 0; i < 4; i++) {
        h[i] = __float2bfloat16(xs[i]);
        l[i] = __float2bfloat16(xs[i] - __bfloat162float(h[i]));
    }
    unsigned long long hp, lp;
    memcpy(&hp, h, 8); memcpy(&lp, l, 8);

    int rt = node >> 7, r = node & 127;
    int ktile = lane >> 4;
    uint32_t sw = SWZ((uint32_t)(r * 128 + (lane & 15) * 8));
    size_t off = ((size_t)rt * 2 + ktile) * 16384 + sw;
    *(unsigned long long*)(g_Ah + off) = hp;
    *(unsigned long long*)(g_Al + off) = lp;
}

// ---------------------------------------------------------------------------
// transform_mma: warp-level bf16 tensor GEMM (mma.sync), 3-product fp32 split
//   D = Ah@Wh^T + Ah@Wl^T + Al@Wh^T   per (row-tile, type) CTA
// ---------------------------------------------------------------------------
#define SMEM_AH 0
#define SMEM_AL 32768
#define SMEM_WH 65536
#define SMEM_WL 98304
#define SMEM_TOTAL 131072

__global__ __launch_bounds__(256, 1)
void transform_mma(int N)
{
    extern __shared__ unsigned char smem[];
    const int tid = threadIdx.x, wid = tid >> 5, lane = tid & 31;
    const int rt = blockIdx.x, t = blockIdx.y;

    // copy 4 x 32KB tiles in (coalesced uint4)
    {
        uint4* d0 = (uint4*)(smem + SMEM_AH);
        uint4* d1 = (uint4*)(smem + SMEM_AL);
        uint4* d2 = (uint4*)(smem + SMEM_WH);
        uint4* d3 = (uint4*)(smem + SMEM_WL);
        const uint4* s0 = (const uint4*)(g_Ah + (size_t)rt * TILE_BYTES);
        const uint4* s1 = (const uint4*)(g_Al + (size_t)rt * TILE_BYTES);
        const uint4* s2 = (const uint4*)(g_Wh + (size_t)t * TILE_BYTES);
        const uint4* s3 = (const uint4*)(g_Wl + (size_t)t * TILE_BYTES);
        #pragma unroll
        for (int i = tid; i < 2048; i += 256) {
            d0[i] = s0[i]; d1[i] = s1[i]; d2[i] = s2[i]; d3[i] = s3[i];
        }
    }
    __syncthreads();

    const uint32_t sb = smem_u32(smem);
    const int wm = wid & 3, wn = wid >> 2;
    const int m_base = wm * 32, n_base = wn * 64;

    float acc[2][8][4];
    #pragma unroll
    for (int mi = 0; mi < 2; mi++)
        #pragma unroll
        for (int nt = 0; nt < 8; nt++)
            #pragma unroll
            for (int q = 0; q < 4; q++) acc[mi][nt][q] = 0.f;

    const int lan15 = lane & 15;
    const int kbyte_hi = (lane >> 4) * 16;   // +8 bf16 cols for lanes 16..31

    #pragma unroll
    for (int prod = 0; prod < 3; prod++) {
        const uint32_t Ab = sb + ((prod == 2) ? SMEM_AL : SMEM_AH);
        const uint32_t Bb = sb + ((prod == 1) ? SMEM_WL : SMEM_WH);
        #pragma unroll
        for (int kt = 0; kt < 8; kt++) {
            const int k0 = kt * 16;
            const uint32_t tb = (uint32_t)(k0 >> 6) * 16384u;
            const int kb = (k0 & 63) * 2 + kbyte_hi;

            uint32_t a[2][4];
            #pragma unroll
            for (int mi = 0; mi < 2; mi++) {
                int row = m_base + mi * 16 + lan15;
                ldsm4(a[mi], Ab + tb + SWZ((uint32_t)(row * 128 + kb)));
            }
            uint32_t b[4][4];
            #pragma unroll
            for (int nt = 0; nt < 4; nt++) {
                int row = n_base + nt * 16 + lan15;
                ldsm4(b[nt], Bb + tb + SWZ((uint32_t)(row * 128 + kb)));
            }
            #pragma unroll
            for (int mi = 0; mi < 2; mi++)
                #pragma unroll
                for (int nt = 0; nt < 4; nt++) {
                    mma_bf16(acc[mi][nt * 2 + 0], a[mi], b[nt][0], b[nt][2]);
                    mma_bf16(acc[mi][nt * 2 + 1], a[mi], b[nt][1], b[nt][3]);
                }
        }
    }

    // epilogue: direct float2 global stores
    const int r = lane >> 2, c = (lane & 3) * 2;
    #pragma unroll
    for (int mi = 0; mi < 2; mi++) {
        #pragma unroll
        for (int half = 0; half < 2; half++) {
            int grow = rt * 128 + m_base + mi * 16 + r + half * 8;
            if (grow >= N) continue;
            float* dst = g_T + ((size_t)t * N + grow) * DD + n_base + c;
            #pragma unroll
            for (int nt = 0; nt < 8; nt++) {
                float2 v;
                v.x = acc[mi][nt][half * 2 + 0];
                v.y = acc[mi][nt][half * 2 + 1];
                *(float2*)(dst + nt * 8) = v;
            }
        }
    }
}

// ---------------------------------------------------------------------------
// Edge kernel: one warp per edge (unchanged — passed R1)
// ---------------------------------------------------------------------------
__global__ __launch_bounds__(256)
void edge_kernel(const int* __restrict__ deprel, const int* __restrict__ deparc,
                 const int* __restrict__ eidx,
                 const float* __restrict__ b_in, const float* __restrict__ b_in_gate,
                 const float* __restrict__ b_out, const float* __restrict__ b_out_gate,
                 float* __restrict__ out, int N, int E)
{
    int e = (int)((blockIdx.x * 256u + threadIdx.x) >> 5);
    if (e >= E) return;
    int lane = threadIdx.x & 31;

    int t  = __ldg(deparc + e);
    int s  = __ldg(eidx + e);
    int tg = __ldg(eidx + E + e);

    float gpre = g_G[(size_t)t * N + s];
    float4 m = *(const float4*)(g_T + ((size_t)t * N + s) * DD + lane * 4);

    float bg = 0.f;
    if (t < 2) {
        int r = __ldg(deprel + e);
        const float* bb = (t == 0) ? b_in : b_out;
        float4 b4 = *(const float4*)(bb + (size_t)r * DD + lane * 4);
        m.x += b4.x; m.y += b4.y; m.z += b4.z; m.w += b4.w;
        bg = (t == 0) ? __ldg(b_in_gate + r) : __ldg(b_out_gate + r);
    }
    float gate = 1.f / (1.f + expf(-(gpre + bg)));
    m.x *= gate; m.y *= gate; m.z *= gate; m.w *= gate;

    float* op = out + (size_t)tg * DD + lane * 4;
    asm volatile("red.global.add.v4.f32 [%0], {%1, %2, %3, %4};"
                 :: "l"(op), "f"(m.x), "f"(m.y), "f"(m.z), "f"(m.w)
                 : "memory");
}

// ---------------------------------------------------------------------------
extern "C" void kernel_launch(void* const* d_in, const int* in_sizes, int n_in,
                              void* d_out, int out_size)
{
    const float* inp         = (const float*)d_in[0];
    const int*   deprel      = (const int*)  d_in[1];
    const int*   deparc      = (const int*)  d_in[2];
    const int*   eidx        = (const int*)  d_in[3];
    const float* V_in        = (const float*)d_in[4];
    const float* b_in        = (const float*)d_in[5];
    const float* V_in_gate   = (const float*)d_in[6];
    const float* b_in_gate   = (const float*)d_in[7];
    const float* V_out       = (const float*)d_in[8];
    const float* b_out       = (const float*)d_in[9];
    const float* V_out_gate  = (const float*)d_in[10];
    const float* b_out_gate  = (const float*)d_in[11];
    const float* W_self      = (const float*)d_in[12];
    const float* W_self_gate = (const float*)d_in[13];
    const float* W_norel     = (const float*)d_in[14];
    const float* W_norel_gate= (const float*)d_in[15];
    (void)n_in;

    const int N = in_sizes[0] / DD;
    const int E = in_sizes[1];
    float* out = (float*)d_out;

    cudaFuncSetAttribute(transform_mma,
                         cudaFuncAttributeMaxDynamicSharedMemorySize, SMEM_TOTAL);

    cudaMemsetAsync(d_out, 0, (size_t)out_size * sizeof(float), 0);

    prep_w<<<64, 256>>>(V_in, V_out, W_self, W_norel);
    prep_nodes<<<(N + 7) / 8, 256>>>(inp, V_in_gate, V_out_gate,
                                     W_self_gate, W_norel_gate, N);

    dim3 tgrid((N + 127) / 128, 4);
    transform_mma<<<tgrid, 256, SMEM_TOTAL>>>(N);

    int eblocks = (E * 32 + 255) / 256;
    edge_kernel<<<eblocks, 256>>>(deprel, deparc, eidx,
                                  b_in, b_in_gate, b_out, b_out_gate,
                                  out, N, E);
}